// round 4
// baseline (speedup 1.0000x reference)
#include <cuda_runtime.h>
#include <cstdint>
#include <cstddef>

#define BB   2
#define TT   2048
#define DD   1024
#define HH   16
#define HDD  64
#define FFD  4096
#define MT   (BB*TT)

// ---------------------------------------------------------------------------
// Scratch
// ---------------------------------------------------------------------------
__device__ float g_h  [MT*DD];
__device__ float g_q  [MT*DD];
__device__ float g_k  [MT*DD];
__device__ float g_v  [MT*DD];
__device__ float g_ao [MT*DD];
__device__ float g_tmp[MT*DD];
__device__ float g_y  [MT*DD];
__device__ float g_mid[MT*FFD];
__device__ float g_w  [12*1024*1024];   // tf32-rounded weights

#define WQ_OFF 0
#define WK_OFF (1024*1024)
#define WV_OFF (2*1024*1024)
#define WO_OFF (3*1024*1024)
#define W1_OFF (4*1024*1024)
#define W2_OFF (8*1024*1024)

// ---------------------------------------------------------------------------
// Helpers
// ---------------------------------------------------------------------------
__device__ __forceinline__ float tf32r(float x) {
    float r; asm("cvt.rna.tf32.f32 %0, %1;" : "=f"(r) : "f"(x)); return r;
}
__device__ __forceinline__ uint32_t smaddr(const void* p) {
    return (uint32_t)__cvta_generic_to_shared(p);
}
#define CP16(dst, src) asm volatile("cp.async.cg.shared.global [%0], [%1], 16;\n" :: "r"(dst), "l"(src))
#define CP_COMMIT()    asm volatile("cp.async.commit_group;\n")

// D += A(16x8) * B(8x8), tf32
__device__ __forceinline__ void mma8(float* d, const float* a, const float* b) {
    asm volatile(
        "mma.sync.aligned.m16n8k8.row.col.f32.tf32.tf32.f32 "
        "{%0,%1,%2,%3}, {%4,%5,%6,%7}, {%8,%9}, {%0,%1,%2,%3};\n"
        : "+f"(d[0]), "+f"(d[1]), "+f"(d[2]), "+f"(d[3])
        : "r"(__float_as_uint(a[0])), "r"(__float_as_uint(a[1])),
          "r"(__float_as_uint(a[2])), "r"(__float_as_uint(a[3])),
          "r"(__float_as_uint(b[0])), "r"(__float_as_uint(b[1])));
}

// ---------------------------------------------------------------------------
// Pack + round ALL weights to tf32 in one launch (segments contiguous in g_w)
// units: float4.  q,k,v,o = 256K each; w1,w2 = 1M each; total 3M float4.
// ---------------------------------------------------------------------------
__global__ void __launch_bounds__(256) pack_kernel(
    const float4* __restrict__ wq, const float4* __restrict__ wk,
    const float4* __restrict__ wv, const float4* __restrict__ wo,
    const float4* __restrict__ w1, const float4* __restrict__ w2,
    float4* __restrict__ out)
{
    int i = blockIdx.x * 256 + threadIdx.x;
    const int Q = 256 * 1024;
    const float4* src; int off;
    if      (i <     Q) { src = wq; off = 0; }
    else if (i < 2 * Q) { src = wk; off = Q; }
    else if (i < 3 * Q) { src = wv; off = 2 * Q; }
    else if (i < 4 * Q) { src = wo; off = 3 * Q; }
    else if (i < 8 * Q) { src = w1; off = 4 * Q; }
    else                { src = w2; off = 8 * Q; }
    float4 v = src[i - off];
    v.x = tf32r(v.x); v.y = tf32r(v.y); v.z = tf32r(v.z); v.w = tf32r(v.w);
    out[i] = v;
}

// ---------------------------------------------------------------------------
// RMSNorm (optionally + residual); RND: round output to tf32
// ---------------------------------------------------------------------------
template <int RND>
__global__ void __launch_bounds__(256) rmsnorm_kernel(
    const float* __restrict__ a, const float* __restrict__ b,
    const float* __restrict__ w, float* __restrict__ out)
{
    int row = blockIdx.x;
    size_t base = (size_t)row * DD;
    float v[4];
    float ss = 0.f;
#pragma unroll
    for (int t = 0; t < 4; t++) {
        int c = threadIdx.x + t * 256;
        float x = a[base + c];
        if (b) x += b[base + c];
        v[t] = x;
        ss += x * x;
    }
    __shared__ float red[8];
#pragma unroll
    for (int o = 16; o; o >>= 1) ss += __shfl_xor_sync(0xffffffffu, ss, o);
    if ((threadIdx.x & 31) == 0) red[threadIdx.x >> 5] = ss;
    __syncthreads();
    if (threadIdx.x == 0) {
        float tot = 0.f;
#pragma unroll
        for (int i = 0; i < 8; i++) tot += red[i];
        red[0] = tot;
    }
    __syncthreads();
    float scale = rsqrtf(red[0] * (1.0f / DD) + 1e-6f);
#pragma unroll
    for (int t = 0; t < 4; t++) {
        int c = threadIdx.x + t * 256;
        float o = v[t] * scale * w[c];
        out[base + c] = RND ? tf32r(o) : o;
    }
}

// ---------------------------------------------------------------------------
// TF32 GEMM: CTA tile 128x256, BK=16, 8 warps x (64x64), 3-stage cp.async.
// N % 256 == 0, M % 128 == 0, K % 16 == 0.
// ---------------------------------------------------------------------------
template <int EPI, int RND>
__global__ void __launch_bounds__(256, 1) tgemm_kernel(
    const float* __restrict__ A, const float* __restrict__ B,
    float* __restrict__ C, int M, int N, int K)
{
    __shared__ float As[3][128 * 20];   // [m][k] stride 20
    __shared__ float Bs[3][16 * 264];   // [k][n] stride 264 (==8 mod 32)

    int tid = threadIdx.x;
    int warp = tid >> 5, lane = tid & 31;
    int g = lane >> 2, tig = lane & 3;
    int wm = (warp >> 2) * 64, wn = (warp & 3) * 64;
    int bx = blockIdx.x, by = blockIdx.y;

    int ar = tid >> 1;            // 0..127
    int ac = (tid & 1) * 8;       // 0 or 8 (two CP16 each)
    int br = tid >> 4;            // 0..15
    int bc = (tid & 15) * 16;     // 0..240 (four CP16 each)

    const float* a_src = A + (size_t)(by * 128 + ar) * K + ac;
    const float* b_src = B + (size_t)br * N + bx * 256 + bc;
    uint32_t a_dst = smaddr(&As[0][ar * 20 + ac]);
    uint32_t b_dst = smaddr(&Bs[0][br * 264 + bc]);

    float acc[4][8][4];
#pragma unroll
    for (int i = 0; i < 4; i++)
#pragma unroll
        for (int j = 0; j < 8; j++)
#pragma unroll
            for (int r = 0; r < 4; r++) acc[i][j][r] = 0.f;

    int KT = K >> 4;

#define ISSUE(stage, kt)                                                     \
    {                                                                        \
        uint32_t ad = a_dst + (stage) * 10240;                               \
        const float* ap = a_src + ((kt) << 4);                               \
        CP16(ad, ap); CP16(ad + 16, ap + 4);                                 \
        uint32_t bd = b_dst + (stage) * 16896;                               \
        const float* bp = b_src + (size_t)((kt) << 4) * N;                   \
        CP16(bd, bp); CP16(bd + 16, bp + 4);                                 \
        CP16(bd + 32, bp + 8); CP16(bd + 48, bp + 12);                       \
        CP_COMMIT();                                                         \
    }

    ISSUE(0, 0);
    if (KT > 1) ISSUE(1, 1);

    int stage = 2;
    for (int kt = 0; kt < KT; kt++) {
        if (kt + 2 < KT) {
            ISSUE(stage, kt + 2);
            stage = (stage + 1 == 3) ? 0 : stage + 1;
            asm volatile("cp.async.wait_group 2;\n");
        } else if (kt + 1 < KT) {
            asm volatile("cp.async.wait_group 1;\n");
        } else {
            asm volatile("cp.async.wait_group 0;\n");
        }
        __syncthreads();

        int buf = kt - (kt / 3) * 3;
        const float* as = As[buf];
        const float* bs = Bs[buf];
#pragma unroll
        for (int ch = 0; ch < 2; ch++) {
            int kb = ch * 8 + tig;
            float a[4][4], b[8][2];
#pragma unroll
            for (int mt = 0; mt < 4; mt++) {
                int m = wm + mt * 16 + g;
                a[mt][0] = as[m * 20 + kb];
                a[mt][1] = as[(m + 8) * 20 + kb];
                a[mt][2] = as[m * 20 + kb + 4];
                a[mt][3] = as[(m + 8) * 20 + kb + 4];
            }
#pragma unroll
            for (int nt = 0; nt < 8; nt++) {
                int n = wn + nt * 8 + g;
                b[nt][0] = bs[kb * 264 + n];
                b[nt][1] = bs[(kb + 4) * 264 + n];
            }
#pragma unroll
            for (int mt = 0; mt < 4; mt++)
#pragma unroll
                for (int nt = 0; nt < 8; nt++) mma8(acc[mt][nt], a[mt], b[nt]);
        }
        __syncthreads();
    }
#undef ISSUE

#pragma unroll
    for (int mt = 0; mt < 4; mt++) {
#pragma unroll
        for (int nt = 0; nt < 8; nt++) {
            int row = by * 128 + wm + mt * 16 + g;
            int col = bx * 256 + wn + nt * 8 + 2 * tig;
            float e[4];
#pragma unroll
            for (int r = 0; r < 4; r++) {
                float c = acc[mt][nt][r];
                if (EPI == 1) c = c / (1.0f + __expf(-c));
                if (RND)      c = tf32r(c);
                e[r] = c;
            }
            *(float2*)&C[(size_t)row * N + col]       = make_float2(e[0], e[1]);
            *(float2*)&C[(size_t)(row + 8) * N + col] = make_float2(e[2], e[3]);
        }
    }
}

// ---------------------------------------------------------------------------
// Flash attention (as round 3)
// ---------------------------------------------------------------------------
__global__ void __launch_bounds__(256) flash_kernel(
    const float* __restrict__ q, const float* __restrict__ k,
    const float* __restrict__ v, float* __restrict__ ao)
{
    int it = blockIdx.x;
    int bh = blockIdx.y;
    int b = bh >> 4, h = bh & 15;
    int i0 = it * 128;

    __shared__ float smem[64 * 68 + 64 * 72];
    float* Ks = smem;
    float* Vs = smem + 64 * 68;
    float* Qstage = smem;

    int tid = threadIdx.x, warp = tid >> 5, lane = tid & 31;
    int g = lane >> 2, tig = lane & 3;

    {
        int r = tid >> 1;
        int cb = (tid & 1) * 32;
        const float* qp = q + (size_t)(b * TT + i0 + r) * DD + h * HDD + cb;
        float* dst = Qstage + r * 68 + cb;
#pragma unroll
        for (int c4 = 0; c4 < 8; c4++)
            *(float4*)(dst + c4 * 4) = *(const float4*)(qp + c4 * 4);
    }
    __syncthreads();
    float qa[8][4];
    {
        int m = warp * 16 + g;
#pragma unroll
        for (int kt = 0; kt < 8; kt++) {
            int kb = kt * 8 + tig;
            qa[kt][0] = Qstage[m * 68 + kb] * 0.125f;
            qa[kt][1] = Qstage[(m + 8) * 68 + kb] * 0.125f;
            qa[kt][2] = Qstage[m * 68 + kb + 4] * 0.125f;
            qa[kt][3] = Qstage[(m + 8) * 68 + kb + 4] * 0.125f;
        }
    }
    __syncthreads();

    float o[8][4];
#pragma unroll
    for (int nt = 0; nt < 8; nt++)
#pragma unroll
        for (int r = 0; r < 4; r++) o[nt][r] = 0.f;
    float rm0 = -1e30f, rm1 = -1e30f, rs0 = 0.f, rs1 = 0.f;

    int jt_max = 2 * it + 1;
    int warp_row0 = i0 + warp * 16;
    int src0 = g * 4 + (tig >> 1);
    int src1 = src0 + 2;
    bool hi = tig & 1;

    for (int jt = 0; jt <= jt_max; jt++) {
        int j0 = jt * 64;
        {
            int r = tid >> 2, cb = (tid & 3) * 16;
            const float* kp = k + (size_t)(b * TT + j0 + r) * DD + h * HDD + cb;
            const float* vp = v + (size_t)(b * TT + j0 + r) * DD + h * HDD + cb;
#pragma unroll
            for (int c4 = 0; c4 < 4; c4++) {
                *(float4*)(Ks + r * 68 + cb + c4 * 4) = *(const float4*)(kp + c4 * 4);
                *(float4*)(Vs + r * 72 + cb + c4 * 4) = *(const float4*)(vp + c4 * 4);
            }
        }
        __syncthreads();

        if (j0 <= warp_row0 + 15) {
            float s[8][4];
#pragma unroll
            for (int nt = 0; nt < 8; nt++)
#pragma unroll
                for (int r = 0; r < 4; r++) s[nt][r] = 0.f;
#pragma unroll
            for (int kt = 0; kt < 8; kt++) {
                int kb = kt * 8 + tig;
#pragma unroll
                for (int nt = 0; nt < 8; nt++) {
                    float bfr[2] = { Ks[(nt * 8 + g) * 68 + kb],
                                     Ks[(nt * 8 + g) * 68 + kb + 4] };
                    mma8(s[nt], qa[kt], bfr);
                }
            }
            int r0 = warp_row0 + g, r1 = r0 + 8;
            if (j0 + 63 > warp_row0) {
#pragma unroll
                for (int nt = 0; nt < 8; nt++) {
                    int j = j0 + nt * 8 + 2 * tig;
                    if (j     > r0) s[nt][0] = -1e30f;
                    if (j + 1 > r0) s[nt][1] = -1e30f;
                    if (j     > r1) s[nt][2] = -1e30f;
                    if (j + 1 > r1) s[nt][3] = -1e30f;
                }
            }
            float m0 = -1e30f, m1 = -1e30f;
#pragma unroll
            for (int nt = 0; nt < 8; nt++) {
                m0 = fmaxf(m0, fmaxf(s[nt][0], s[nt][1]));
                m1 = fmaxf(m1, fmaxf(s[nt][2], s[nt][3]));
            }
            m0 = fmaxf(m0, __shfl_xor_sync(0xffffffffu, m0, 1));
            m0 = fmaxf(m0, __shfl_xor_sync(0xffffffffu, m0, 2));
            m1 = fmaxf(m1, __shfl_xor_sync(0xffffffffu, m1, 1));
            m1 = fmaxf(m1, __shfl_xor_sync(0xffffffffu, m1, 2));
            float nm0 = fmaxf(rm0, m0), nm1 = fmaxf(rm1, m1);
            float al0 = __expf(rm0 - nm0), al1 = __expf(rm1 - nm1);
            rm0 = nm0; rm1 = nm1;
            float l0 = 0.f, l1 = 0.f;
#pragma unroll
            for (int nt = 0; nt < 8; nt++) {
                s[nt][0] = tf32r(__expf(s[nt][0] - nm0));
                s[nt][1] = tf32r(__expf(s[nt][1] - nm0));
                s[nt][2] = tf32r(__expf(s[nt][2] - nm1));
                s[nt][3] = tf32r(__expf(s[nt][3] - nm1));
                l0 += s[nt][0] + s[nt][1];
                l1 += s[nt][2] + s[nt][3];
            }
            l0 += __shfl_xor_sync(0xffffffffu, l0, 1);
            l0 += __shfl_xor_sync(0xffffffffu, l0, 2);
            l1 += __shfl_xor_sync(0xffffffffu, l1, 1);
            l1 += __shfl_xor_sync(0xffffffffu, l1, 2);
            rs0 = rs0 * al0 + l0;
            rs1 = rs1 * al1 + l1;
#pragma unroll
            for (int nt = 0; nt < 8; nt++) {
                o[nt][0] *= al0; o[nt][1] *= al0;
                o[nt][2] *= al1; o[nt][3] *= al1;
            }
#pragma unroll
            for (int kt = 0; kt < 8; kt++) {
                float v00 = __shfl_sync(0xffffffffu, s[kt][0], src0);
                float v01 = __shfl_sync(0xffffffffu, s[kt][1], src0);
                float v02 = __shfl_sync(0xffffffffu, s[kt][2], src0);
                float v03 = __shfl_sync(0xffffffffu, s[kt][3], src0);
                float v10 = __shfl_sync(0xffffffffu, s[kt][0], src1);
                float v11 = __shfl_sync(0xffffffffu, s[kt][1], src1);
                float v12 = __shfl_sync(0xffffffffu, s[kt][2], src1);
                float v13 = __shfl_sync(0xffffffffu, s[kt][3], src1);
                float a[4];
                a[0] = hi ? v01 : v00;
                a[1] = hi ? v03 : v02;
                a[2] = hi ? v11 : v10;
                a[3] = hi ? v13 : v12;
                int kb = kt * 8 + tig;
#pragma unroll
                for (int nt = 0; nt < 8; nt++) {
                    float bfr[2] = { Vs[kb * 72 + nt * 8 + g],
                                     Vs[(kb + 4) * 72 + nt * 8 + g] };
                    mma8(o[nt], a, bfr);
                }
            }
        }
        __syncthreads();
    }

    float inv0 = 1.0f / rs0, inv1 = 1.0f / rs1;
    int r0 = i0 + warp * 16 + g;
#pragma unroll
    for (int nt = 0; nt < 8; nt++) {
        int col = h * HDD + nt * 8 + 2 * tig;
        float* p0 = ao + (size_t)(b * TT + r0) * DD + col;
        float* p1 = ao + (size_t)(b * TT + r0 + 8) * DD + col;
        *(float2*)p0 = make_float2(tf32r(o[nt][0] * inv0), tf32r(o[nt][1] * inv0));
        *(float2*)p1 = make_float2(tf32r(o[nt][2] * inv1), tf32r(o[nt][3] * inv1));
    }
}

// ---------------------------------------------------------------------------
// Launch
// ---------------------------------------------------------------------------
extern "C" void kernel_launch(void* const* d_in, const int* in_sizes, int n_in,
                              void* d_out, int out_size)
{
    const float* x      = (const float*)d_in[0];
    const float* w_pre  = (const float*)d_in[1];
    const float* wq     = (const float*)d_in[2];
    const float* wk     = (const float*)d_in[3];
    const float* wv     = (const float*)d_in[4];
    const float* wo     = (const float*)d_in[5];
    const float* w_attn = (const float*)d_in[6];
    const float* w1     = (const float*)d_in[7];
    const float* w2     = (const float*)d_in[8];
    const float* w_ffn  = (const float*)d_in[9];
    float* out = (float*)d_out;

    float *h_, *q_, *k_, *v_, *ao_, *tmp_, *y_, *mid_, *w_;
    cudaGetSymbolAddress((void**)&h_,   g_h);
    cudaGetSymbolAddress((void**)&q_,   g_q);
    cudaGetSymbolAddress((void**)&k_,   g_k);
    cudaGetSymbolAddress((void**)&v_,   g_v);
    cudaGetSymbolAddress((void**)&ao_,  g_ao);
    cudaGetSymbolAddress((void**)&tmp_, g_tmp);
    cudaGetSymbolAddress((void**)&y_,   g_y);
    cudaGetSymbolAddress((void**)&mid_, g_mid);
    cudaGetSymbolAddress((void**)&w_,   g_w);

    // 0) round all weights to tf32 in one launch
    pack_kernel<<<12288, 256>>>((const float4*)wq, (const float4*)wk,
                                (const float4*)wv, (const float4*)wo,
                                (const float4*)w1, (const float4*)w2,
                                (float4*)w_);

    // 1) h = rmsnorm(x)
    rmsnorm_kernel<1><<<MT, 256>>>(x, nullptr, w_pre, h_);

    // 2) q, k, v projections
    {
        dim3 g(DD / 256, MT / 128);
        tgemm_kernel<0, 1><<<g, 256>>>(h_, w_ + WQ_OFF, q_, MT, DD, DD);
        tgemm_kernel<0, 1><<<g, 256>>>(h_, w_ + WK_OFF, k_, MT, DD, DD);
        tgemm_kernel<0, 1><<<g, 256>>>(h_, w_ + WV_OFF, v_, MT, DD, DD);
    }

    // 3) fused flash attention
    {
        dim3 g(TT / 128, BB * HH);
        flash_kernel<<<g, 256>>>(q_, k_, v_, ao_);
    }

    // 4) o-proj + residual norm
    {
        dim3 g(DD / 256, MT / 128);
        tgemm_kernel<0, 0><<<g, 256>>>(ao_, w_ + WO_OFF, tmp_, MT, DD, DD);
    }
    rmsnorm_kernel<1><<<MT, 256>>>(h_, tmp_, w_attn, y_);

    // 5) FFN
    {
        dim3 g(FFD / 256, MT / 128);
        tgemm_kernel<1, 1><<<g, 256>>>(y_, w_ + W1_OFF, mid_, MT, FFD, DD);
    }
    {
        dim3 g(DD / 256, MT / 128);
        tgemm_kernel<0, 0><<<g, 256>>>(mid_, w_ + W2_OFF, tmp_, MT, DD, FFD);
    }
    rmsnorm_kernel<0><<<MT, 256>>>(y_, tmp_, w_ffn, out);
}